// round 16
// baseline (speedup 1.0000x reference)
#include <cuda_runtime.h>
#include <cuda_bf16.h>
#include <cstdint>

#define Bn 64
#define Ln 2048
#define Hn 128
#define On 128
#define Nn 256
#define TS 64            // t-steps per stage (GEMM K per block)
#define NTB 11           // max stages (covers K<=704)
#define LOG_INV_EPS 6.9077553f   // eps = 1e-3

// device globals (module-scope, zero-initialized; no allocation allowed)
__device__ float2 g_lam[Nn];
__device__ float  g_gam[Nn];
__device__ int    g_order[Nn];           // ranks -> mode id, K descending
__device__ int    g_gsteps[8];           // stages per 32-mode group
__device__ float2 g_wseg[Nn * NTB];      // lam^(64 s)
__device__ __nv_bfloat16 g_Vhi[NTB * 8 * 4096];  // V tiles [s][g]: 64 rows x 64 k
__device__ __nv_bfloat16 g_Vlo[NTB * 8 * 4096];
__device__ __nv_bfloat16 g_Uhi[Bn * NTB * 8192]; // U tiles [b][s]: 128 h x 64 k
__device__ __nv_bfloat16 g_Ulo[Bn * NTB * 8192];
__device__ float2 g_xp[Bn * Nn * 16];    // stage partials (unwritten slots stay 0)
__device__ float4 g_Cp[(Nn / 2) * On];   // packed C^T
__device__ float4 g_Dp[(Hn / 4) * On];   // packed D^T

__device__ __forceinline__ void mma16816(float* d, const unsigned* a,
                                         unsigned b0, unsigned b1) {
    asm volatile(
        "mma.sync.aligned.m16n8k16.row.col.f32.bf16.bf16.f32 "
        "{%0,%1,%2,%3}, {%4,%5,%6,%7}, {%8,%9}, {%0,%1,%2,%3};"
        : "+f"(d[0]), "+f"(d[1]), "+f"(d[2]), "+f"(d[3])
        : "r"(a[0]), "r"(a[1]), "r"(a[2]), "r"(a[3]), "r"(b0), "r"(b1));
}

// ---------------- prep: params/sort (block 0) + C/D transpose ----------------
__global__ void __launch_bounds__(256) prep_kernel(const float* __restrict__ nu_log,
    const float* __restrict__ theta_log, const float* __restrict__ gamma_log,
    const float* __restrict__ C_re, const float* __restrict__ C_im,
    const float* __restrict__ D)
{
    const int bx = blockIdx.x, tid = threadIdx.x;
    if (bx == 0) {
        int n = tid;
        float a = expf(nu_log[n]);
        float th = expf(theta_log[n]);
        float r = expf(-a);
        float sn, cs;
        sincosf(th, &sn, &cs);
        float lre = r * cs, lim = r * sn;
        g_lam[n] = make_float2(lre, lim);
        g_gam[n] = expf(gamma_log[n]);
        int K = (int)(LOG_INV_EPS / a) + 1;
        if (K > NTB * TS) K = NTB * TS;   // coverage cap (always >= true horizon)
        if (K < 1) K = 1;

        float pre = lre, pim = lim;       // lam^64 via 6 squarings
#pragma unroll
        for (int i = 0; i < 6; ++i) {
            float t = fmaf(pre, pre, -pim * pim);
            pim = 2.0f * pre * pim;
            pre = t;
        }
        float wre = 1.0f, wim = 0.0f;
#pragma unroll
        for (int s = 0; s < NTB; ++s) {
            g_wseg[n * NTB + s] = make_float2(wre, wim);
            float t = fmaf(wre, pre, -wim * pim);
            wim = fmaf(wre, pim, wim * pre);
            wre = t;
        }

        __shared__ int sK[Nn], sOrd[Nn];
        sK[n] = K;
        __syncthreads();
        int rank = 0;
        for (int j = 0; j < Nn; ++j) {
            int Kj = sK[j];
            if (Kj > K || (Kj == K && j < n)) rank++;
        }
        g_order[rank] = n;
        sOrd[rank] = n;
        __syncthreads();
        if (n < 8) {
            int st = (sK[sOrd[n * 32]] + TS - 1) / TS;   // group head = group max
            if (st > NTB) st = NTB;
            g_gsteps[n] = st;
        }
    } else if (bx <= 32) {
        const int t = bx - 1, o0 = (t & 3) * 32, n0 = (t >> 2) * 32;
        const int tx = tid & 31, ty = tid >> 5;
        __shared__ float2 tile[32][33];
#pragma unroll
        for (int r = 0; r < 4; ++r) {
            int o = o0 + ty + 8 * r;
            tile[ty + 8 * r][tx] = make_float2(C_re[(size_t)o * Nn + n0 + tx],
                                               C_im[(size_t)o * Nn + n0 + tx]);
        }
        __syncthreads();
#pragma unroll
        for (int r = 0; r < 2; ++r) {
            int p = ty + 8 * r;
            float2 a0 = tile[tx][2 * p], a1 = tile[tx][2 * p + 1];
            g_Cp[(size_t)((n0 >> 1) + p) * On + o0 + tx] =
                make_float4(a0.x, a0.y, a1.x, a1.y);
        }
    } else {
        const int t = bx - 33, o0 = (t & 3) * 32, h0 = (t >> 2) * 32;
        const int tx = tid & 31, ty = tid >> 5;
        __shared__ float tile[32][33];
#pragma unroll
        for (int r = 0; r < 4; ++r)
            tile[ty + 8 * r][tx] = D[(size_t)(o0 + ty + 8 * r) * Hn + h0 + tx];
        __syncthreads();
        g_Dp[(size_t)((h0 >> 2) + ty) * On + o0 + tx] =
            make_float4(tile[tx][4 * ty], tile[tx][4 * ty + 1],
                        tile[tx][4 * ty + 2], tile[tx][4 * ty + 3]);
    }
}

// ---- vbuild: V tiles [s][g]: 64 rows (reim of 32 modes) x 64 k, hi/lo ------
__global__ void __launch_bounds__(256) vbuild_kernel()
{
    const int s = blockIdx.x, j = threadIdx.x, g = j >> 5, m = j & 31;
    if (s >= g_gsteps[g]) return;
    const int n = g_order[j];
    const float2 w0 = g_wseg[n * NTB + s];
    const float gam = g_gam[n];
    const float2 lam = g_lam[n];
    float vr = w0.x * gam, vi = w0.y * gam;

    __nv_bfloat16* base = g_Vhi + (size_t)(s * 8 + g) * 4096;
    __nv_bfloat16* basl = g_Vlo + (size_t)(s * 8 + g) * 4096;
    __nv_bfloat16* rh = base + (size_t)(2 * m) * 64;      // re row
    __nv_bfloat16* rl = basl + (size_t)(2 * m) * 64;
    __nv_bfloat16* ih = base + (size_t)(2 * m + 1) * 64;  // im row
    __nv_bfloat16* il = basl + (size_t)(2 * m + 1) * 64;

    for (int c = 0; c < 8; ++c) {
        __nv_bfloat16 a0[8], a1[8], a2[8], a3[8];
#pragma unroll
        for (int e = 0; e < 8; ++e) {
            a0[e] = __float2bfloat16(vr);
            a1[e] = __float2bfloat16(vr - __bfloat162float(a0[e]));
            a2[e] = __float2bfloat16(vi);
            a3[e] = __float2bfloat16(vi - __bfloat162float(a2[e]));
            float t = fmaf(vr, lam.x, -vi * lam.y);
            vi = fmaf(vr, lam.y, vi * lam.x);
            vr = t;
        }
        *(uint4*)(rh + c * 8) = *(const uint4*)a0;
        *(uint4*)(rl + c * 8) = *(const uint4*)a1;
        *(uint4*)(ih + c * 8) = *(const uint4*)a2;
        *(uint4*)(il + c * 8) = *(const uint4*)a3;
    }
}

// ---- uconv: U tiles [b][s]: row h (128), col t (64): u[b, L-1-64s-t, h] ----
__global__ void __launch_bounds__(128) uconv_kernel(const float* __restrict__ u)
{
    const int s = blockIdx.x, b = blockIdx.y, h = threadIdx.x;
    if (s >= g_gsteps[0]) return;
    __nv_bfloat16* bh = g_Uhi + ((size_t)b * NTB + s) * 8192 + (size_t)h * 64;
    __nv_bfloat16* bl = g_Ulo + ((size_t)b * NTB + s) * 8192 + (size_t)h * 64;
    const float* up = u + ((size_t)b * Ln + (Ln - 1 - s * TS)) * Hn + h;
    for (int c = 0; c < 8; ++c) {
        __nv_bfloat16 hv[8], lv[8];
#pragma unroll
        for (int e = 0; e < 8; ++e) {
            float v = up[-(ptrdiff_t)(c * 8 + e) * Hn];
            hv[e] = __float2bfloat16(v);
            lv[e] = __float2bfloat16(v - __bfloat162float(hv[e]));
        }
        *(uint4*)(bh + c * 8) = *(const uint4*)hv;
        *(uint4*)(bl + c * 8) = *(const uint4*)lv;
    }
}

// ---- mma: block (g, b, z): S[64 reim rows x 128 h] over t in [64z, 64z+64) -
// 4 warps; warp wid owns rows wid*16..+15. HMMA m16n8k16 bf16, 3 hi/lo
// products, fp32 register accumulators. Epilogue dots with B_re/B_im give
// x partials for this stage directly.
__global__ void __launch_bounds__(128) mma_kernel(const float* __restrict__ B_re,
                                                  const float* __restrict__ B_im,
                                                  float2* __restrict__ xp)
{
    const int g = blockIdx.x, b = blockIdx.y, z = blockIdx.z;
    if (z >= g_gsteps[g]) return;
    const int tid = threadIdx.x, wid = tid >> 5, lane = tid & 31;
    const int gq = lane >> 2, tq = lane & 3;

    const __nv_bfloat16* Vh = g_Vhi + (size_t)(z * 8 + g) * 4096;
    const __nv_bfloat16* Vl = g_Vlo + (size_t)(z * 8 + g) * 4096;
    const __nv_bfloat16* Uh = g_Uhi + ((size_t)b * NTB + z) * 8192;
    const __nv_bfloat16* Ul = g_Ulo + ((size_t)b * NTB + z) * 8192;

    float d[16][4];
#pragma unroll
    for (int nt = 0; nt < 16; ++nt)
#pragma unroll
        for (int i = 0; i < 4; ++i) d[nt][i] = 0.f;

    const int r0 = wid * 16 + gq;      // A rows r0 and r0+8
#pragma unroll
    for (int ks = 0; ks < 4; ++ks) {
        const int k0 = ks * 16 + 2 * tq;
        unsigned ah[4], al[4];
        ah[0] = *(const unsigned*)(Vh + (size_t)r0 * 64 + k0);
        ah[1] = *(const unsigned*)(Vh + (size_t)(r0 + 8) * 64 + k0);
        ah[2] = *(const unsigned*)(Vh + (size_t)r0 * 64 + k0 + 8);
        ah[3] = *(const unsigned*)(Vh + (size_t)(r0 + 8) * 64 + k0 + 8);
        al[0] = *(const unsigned*)(Vl + (size_t)r0 * 64 + k0);
        al[1] = *(const unsigned*)(Vl + (size_t)(r0 + 8) * 64 + k0);
        al[2] = *(const unsigned*)(Vl + (size_t)r0 * 64 + k0 + 8);
        al[3] = *(const unsigned*)(Vl + (size_t)(r0 + 8) * 64 + k0 + 8);
#pragma unroll
        for (int nt = 0; nt < 16; ++nt) {
            const __nv_bfloat16* uh = Uh + (size_t)(nt * 8 + gq) * 64 + k0;
            const __nv_bfloat16* ul = Ul + (size_t)(nt * 8 + gq) * 64 + k0;
            unsigned bh0 = *(const unsigned*)uh;
            unsigned bh1 = *(const unsigned*)(uh + 8);
            unsigned bl0 = *(const unsigned*)ul;
            unsigned bl1 = *(const unsigned*)(ul + 8);
            mma16816(d[nt], ah, bh0, bh1);   // hi*hi
            mma16816(d[nt], ah, bl0, bl1);   // hi*lo
            mma16816(d[nt], al, bh0, bh1);   // lo*hi
        }
    }

    // epilogue: rows r0 (mode j0) and r0+8 (mode j1 = j0+4)
    const int j0 = g * 32 + ((wid * 16 + gq) >> 1);
    const int j1 = j0 + 4;
    const int n0 = g_order[j0], n1 = g_order[j1];
    const float* br0 = B_re + (size_t)n0 * Hn;
    const float* bi0 = B_im + (size_t)n0 * Hn;
    const float* br1 = B_re + (size_t)n1 * Hn;
    const float* bi1 = B_im + (size_t)n1 * Hn;

    float A0 = 0.f, B0 = 0.f, A1 = 0.f, B1 = 0.f;
#pragma unroll
    for (int nt = 0; nt < 16; ++nt) {
        const int h = nt * 8 + 2 * tq;
        float2 r0v = *(const float2*)(br0 + h);
        float2 i0v = *(const float2*)(bi0 + h);
        float2 r1v = *(const float2*)(br1 + h);
        float2 i1v = *(const float2*)(bi1 + h);
        A0 = fmaf(d[nt][0], r0v.x, fmaf(d[nt][1], r0v.y, A0));
        B0 = fmaf(d[nt][0], i0v.x, fmaf(d[nt][1], i0v.y, B0));
        A1 = fmaf(d[nt][2], r1v.x, fmaf(d[nt][3], r1v.y, A1));
        B1 = fmaf(d[nt][2], i1v.x, fmaf(d[nt][3], i1v.y, B1));
    }
    // reduce over quad (tq = 0..3)
#pragma unroll
    for (int off = 2; off >= 1; off >>= 1) {
        A0 += __shfl_down_sync(0xffffffffu, A0, off, 4);
        B0 += __shfl_down_sync(0xffffffffu, B0, off, 4);
        A1 += __shfl_down_sync(0xffffffffu, A1, off, 4);
        B1 += __shfl_down_sync(0xffffffffu, B1, off, 4);
    }
    // parity partner (row r0^1) lives at lane xor 4
    float oA0 = __shfl_xor_sync(0xffffffffu, A0, 4);
    float oB0 = __shfl_xor_sync(0xffffffffu, B0, 4);
    float oA1 = __shfl_xor_sync(0xffffffffu, A1, 4);
    float oB1 = __shfl_xor_sync(0xffffffffu, B1, 4);

    if (tq == 0 && !(gq & 1)) {
        // my rows are RE rows: x = (S_re.Bre - S_im.Bim, S_re.Bim + S_im.Bre)
        xp[((size_t)b * Nn + n0) * 16 + z] = make_float2(A0 - oB0, B0 + oA0);
        xp[((size_t)b * Nn + n1) * 16 + z] = make_float2(A1 - oB1, B1 + oA1);
    }
}

// ---------------- out: y = Re(C x) + D u_last -------------------------------
__global__ void __launch_bounds__(128) out_kernel(const float* __restrict__ u,
                                                  float* __restrict__ out)
{
    const int b = blockIdx.x, o = threadIdx.x;
    __shared__ float2 sx[Nn];
    __shared__ float su[Hn];
    for (int i = threadIdx.x; i < Nn; i += 128) {
        const float4* pp = (const float4*)&g_xp[((size_t)b * Nn + i) * 16];
        float xr = 0.f, xi = 0.f;
#pragma unroll
        for (int q = 0; q < 8; ++q) {
            float4 p = pp[q];
            xr += p.x + p.z;
            xi += p.y + p.w;
        }
        sx[i] = make_float2(xr, xi);
    }
    su[o] = u[((size_t)b * Ln + (Ln - 1)) * Hn + o];
    __syncthreads();

    float y0 = 0.f, y1 = 0.f;
#pragma unroll 8
    for (int p = 0; p < Nn / 2; ++p) {
        float4 cv = g_Cp[(size_t)p * On + o];
        float2 x0 = sx[2 * p], x1 = sx[2 * p + 1];
        y0 = fmaf(cv.x, x0.x, y0);
        y1 = fmaf(-cv.y, x0.y, y1);
        y0 = fmaf(cv.z, x1.x, y0);
        y1 = fmaf(-cv.w, x1.y, y1);
    }
#pragma unroll 4
    for (int q = 0; q < Hn / 4; ++q) {
        float4 dv = g_Dp[(size_t)q * On + o];
        y0 = fmaf(dv.x, su[4 * q], y0);
        y1 = fmaf(dv.y, su[4 * q + 1], y1);
        y0 = fmaf(dv.z, su[4 * q + 2], y0);
        y1 = fmaf(dv.w, su[4 * q + 3], y1);
    }
    out[b * On + o] = y0 + y1;
}

// ---------------- launch -----------------------------------------------------
extern "C" void kernel_launch(void* const* d_in, const int* in_sizes, int n_in,
                              void* d_out, int out_size)
{
    const float* u         = (const float*)d_in[2];
    const float* nu_log    = (const float*)d_in[3];
    const float* theta_log = (const float*)d_in[4];
    const float* gamma_log = (const float*)d_in[5];
    const float* B_re      = (const float*)d_in[6];
    const float* B_im      = (const float*)d_in[7];
    const float* C_re      = (const float*)d_in[8];
    const float* C_im      = (const float*)d_in[9];
    const float* Dm        = (const float*)d_in[10];
    float*       out       = (float*)d_out;

    float2* xp;
    cudaGetSymbolAddress((void**)&xp, g_xp);

    prep_kernel<<<49, 256>>>(nu_log, theta_log, gamma_log, C_re, C_im, Dm);
    vbuild_kernel<<<NTB, 256>>>();
    uconv_kernel<<<dim3(NTB, Bn), 128>>>(u);
    mma_kernel<<<dim3(8, Bn, NTB), 128>>>(B_re, B_im, xp);
    out_kernel<<<Bn, 128>>>(u, out);
}